// round 10
// baseline (speedup 1.0000x reference)
#include <cuda_runtime.h>

// AvgPool2d 64x64, stride 1, replicate edge-pad. x: (16,64,256,256) fp32.
// v4 pipeline (16-row batches, register-only horizontal scan into a 96-row
// smem ring, one __syncthreads/batch) with the OUTPUT PATH routed through
// TMA bulk stores: consumers write each batch's 16 output rows (16 KB) to a
// double-buffered smem staging area; one thread issues
// cp.async.bulk.global.shared::cta per batch -> deep contiguous write bursts
// at the memory controller instead of fine-grained STG interleaved with LDG.
// Edge rows (y16..31, y224..255) go via direct STG. 108 KB smem, 2 CTAs/SM.

#define IMG_ELEMS 65536        // 256*256
#define HSTR 196               // float4-aligned H rows
#define RING 96                // 6 batches of 16 rows
#define STAGE_FLOATS 4096      // 16 rows x 256 cols
#define STAGE_OFF (RING * HSTR)
#define SMEM_BYTES ((RING * HSTR + 2 * STAGE_FLOATS) * 4)   // 108032 B

__device__ __forceinline__ unsigned smem_u32(const void* p) {
    return (unsigned)__cvta_generic_to_shared(p);
}

__device__ __forceinline__ void scan_store(float4 va, float4 vb,
                                           float* Hrow, int lane) {
    float p0 = va.x;
    float p1 = p0 + va.y;
    float p2 = p1 + va.z;
    float p3 = p2 + va.w;
    float p4 = p3 + vb.x;
    float p5 = p4 + vb.y;
    float p6 = p5 + vb.z;
    float p7 = p6 + vb.w;

    float t = p7;
    #pragma unroll
    for (int o = 1; o < 32; o <<= 1) {
        float u = __shfl_up_sync(0xffffffffu, t, o);
        if (lane >= o) t += u;
    }
    const float e = t - p7;                   // global prefix at 8*lane-1

    p0 += e; p1 += e; p2 += e; p3 += e;
    p4 += e; p5 += e; p6 += e; p7 += e;

    // H[8l] = q7(lane l+7) - e ; H[8l+k] = q_{k-1}(lane l+8) - q_{k-1}
    float s7 = __shfl_down_sync(0xffffffffu, p7, 7);
    float s0 = __shfl_down_sync(0xffffffffu, p0, 8);
    float s1 = __shfl_down_sync(0xffffffffu, p1, 8);
    float s2 = __shfl_down_sync(0xffffffffu, p2, 8);
    float s3 = __shfl_down_sync(0xffffffffu, p3, 8);
    float s4 = __shfl_down_sync(0xffffffffu, p4, 8);
    float s5 = __shfl_down_sync(0xffffffffu, p5, 8);
    float s6 = __shfl_down_sync(0xffffffffu, p6, 8);

    if (lane < 24) {
        float4 v0 = make_float4(s7 - e,  s0 - p0, s1 - p1, s2 - p2);
        float4 v1 = make_float4(s3 - p3, s4 - p4, s5 - p5, s6 - p6);
        float4* hp = (float4*)(Hrow + 8 * lane);
        hp[0] = v0;
        hp[1] = v1;
    } else if (lane == 24) {
        Hrow[192] = s7 - e;                   // lane 24: t31 - t23 = H[192]
    }
}

__global__ __launch_bounds__(512, 2)
void avgpool64_v8(const float* __restrict__ x, float* __restrict__ out) {
    extern __shared__ float Hs[];             // ring [RING][HSTR] + staging
    float* stageBase = Hs + STAGE_OFF;        // [2][STAGE_FLOATS]

    const int tid  = threadIdx.x;
    const int wid  = tid >> 5;
    const int lane = tid & 31;

    const float* img    = x   + (size_t)blockIdx.x * IMG_ELEMS;
    float*       outImg = out + (size_t)blockIdx.x * IMG_ELEMS;

    // consumer state (threads 0..255 own output column j)
    const int j = tid & 255;
    int cj = j - 31;
    cj = cj < 0 ? 0 : (cj > 192 ? 192 : cj);
    const float* Hcj = Hs + cj;
    float vs = 0.0f;
    const float inv = 1.0f / 4096.0f;

    const float4* rp = (const float4*)img + lane * 2;
    float4 a = rp[wid * 64];
    float4 b = rp[wid * 64 + 1];

    int base = 0;                             // (16*bt) % RING
    #pragma unroll 1
    for (int bt = 0; bt < 16; ++bt) {
        const int r = bt * 16 + wid;

        // ---------------- producers (all 16 warps) ----------------
        float4 ca = a, cb = b;
        if (bt < 15) {                        // prefetch next batch
            a = rp[(r + 16) * 64];
            b = rp[(r + 16) * 64 + 1];
        }
        scan_store(ca, cb, Hs + (base + wid) * HSTR, lane);

        // drain TMA(bt-2) so staging slot (bt&1) is reusable after the barrier
        if (tid == 0)
            asm volatile("cp.async.bulk.wait_group 0;" ::: "memory");

        __syncthreads();   // H(bt) + stage(bt-1) visible; TMA drained

        // issue TMA for stage(bt-1) (written last batch, slot (bt-1)&1)
        if (tid == 0 && bt >= 4) {
            asm volatile("fence.proxy.async.shared::cta;" ::: "memory");
            unsigned src = smem_u32(stageBase + ((bt - 1) & 1) * STAGE_FLOATS);
            // stage(3) -> y0..15 ; stage(m>=4) -> y 16m-32 -> (m-2)*4096 floats
            float* dst = outImg + ((bt == 4) ? 0 : (size_t)(bt - 3) * 4096);
            asm volatile(
                "cp.async.bulk.global.shared::cta.bulk_group [%0], [%1], %2;"
                :: "l"(dst), "r"(src), "r"(16384) : "memory");
            asm volatile("cp.async.bulk.commit_group;" ::: "memory");
        }

        // ---------------- consumer (threads 0..255) ----------------
        if (tid < 256) {
            const float* Hn = Hcj + base * HSTR;          // batch bt rows
            if (bt < 3) {                                 // warmup rows 0..47
                #pragma unroll
                for (int k = 0; k < 16; ++k)
                    vs += Hn[k * HSTR];
            } else if (bt == 3) {                         // finish warmup
                #pragma unroll
                for (int k = 0; k < 16; ++k)
                    vs += Hn[k * HSTR];
                float v = vs * inv;                       // box[0]
                float* st = stageBase + 1 * STAGE_FLOATS + j;  // slot 3&1=1
                #pragma unroll
                for (int k = 0; k < 16; ++k)              // stage y 0..15
                    st[k * 256] = v;
                #pragma unroll
                for (int y = 16; y < 32; ++y)             // direct y 16..31
                    outImg[y * 256 + j] = v;
            } else {                                      // boxes 16bt-63..16bt-48
                int so = base + 32;                       // batch bt-4 slots
                if (so >= RING) so -= RING;
                const float* Ho = Hcj + so * HSTR;
                float* st = stageBase + (bt & 1) * STAGE_FLOATS + j;
                #pragma unroll
                for (int k = 0; k < 16; ++k) {
                    vs += Hn[k * HSTR] - Ho[k * HSTR];
                    st[k * 256] = vs * inv;               // stage y 16bt-32+k
                }
            }
        }

        base += 16;
        if (base >= RING) base -= RING;
    }

    __syncthreads();   // stage(15) STS visible to tid0

    if (tid == 0) {    // issue final chunk: stage(15) -> y 208..223
        asm volatile("fence.proxy.async.shared::cta;" ::: "memory");
        unsigned src = smem_u32(stageBase + 1 * STAGE_FLOATS);   // 15&1 = 1
        float* dst = outImg + (size_t)13 * 4096;
        asm volatile(
            "cp.async.bulk.global.shared::cta.bulk_group [%0], [%1], %2;"
            :: "l"(dst), "r"(src), "r"(16384) : "memory");
        asm volatile("cp.async.bulk.commit_group;" ::: "memory");
    }

    if (tid < 256) {   // box[192] replicate -> y 224..255 (direct STG)
        float v = vs * inv;
        #pragma unroll
        for (int y = 224; y < 256; ++y)
            outImg[y * 256 + j] = v;
    }

    if (tid == 0)
        asm volatile("cp.async.bulk.wait_group 0;" ::: "memory");
    __syncthreads();   // all TMA stores complete before any thread exits
}

extern "C" void kernel_launch(void* const* d_in, const int* in_sizes, int n_in,
                              void* d_out, int out_size) {
    const float* x = (const float*)d_in[0];
    float* out = (float*)d_out;
    const int n_images = in_sizes[0] / IMG_ELEMS;   // 16*64 = 1024

    cudaFuncSetAttribute(avgpool64_v8,
                         cudaFuncAttributeMaxDynamicSharedMemorySize, SMEM_BYTES);
    avgpool64_v8<<<n_images, 512, SMEM_BYTES>>>(x, out);
}

// round 11
// speedup vs baseline: 1.1060x; 1.1060x over previous
#include <cuda_runtime.h>

// AvgPool2d 64x64, stride 1, replicate edge-pad. x: (16,64,256,256) fp32.
// One CTA per (n,c) image, 16-batch pipeline. Phase 1 computes horizontal
// 64-window sums ENTIRELY in registers (warp scan + cross-lane shuffle
// differences), storing H rows straight into a 96-row smem ring with two
// STS.128 per lane. One __syncthreads per batch (ring slack covers the
// store(b+1) / vertical(b) overlap). 256 threads slide per-column vertical
// 64-window sums and write coalesced output rows.
// FINAL: best measured configuration of the series (94.37 us wall, 90.6 ncu);
// six structural variants (bigger batches, 3 CTAs/SM, cache hints, warp
// specialization, tail shaping, TMA burst stores) all measured neutral or
// worse -> plateau at ~5.7 TB/s effective mixed R/W throughput.

#define IMG_ELEMS 65536        // 256*256
#define HSTR 196               // 196 ≡ 0 mod 4 -> float4-aligned H rows
#define RING 96                // 64-row window + 16-row batch + 16 slack
#define SMEM_BYTES (RING * HSTR * 4)   // 75264 B -> 2 CTAs/SM

__global__ __launch_bounds__(512, 2)
void avgpool64_v3(const float* __restrict__ x, float* __restrict__ out) {
    extern __shared__ float Hs[];                 // [RING][HSTR]

    const int tid  = threadIdx.x;
    const int wid  = tid >> 5;
    const int lane = tid & 31;

    const float* img    = x   + (size_t)blockIdx.x * IMG_ELEMS;
    float*       outImg = out + (size_t)blockIdx.x * IMG_ELEMS;

    // vertical state (threads 0..255 own output column tid)
    int cj = tid - 31;
    cj = cj < 0 ? 0 : (cj > 192 ? 192 : cj);
    float vs = 0.0f;
    const float inv = 1.0f / 4096.0f;

    const float4* rp = (const float4*)img;        // 64 float4 per image row
    float4 a = rp[wid * 64 + lane * 2];
    float4 b = rp[wid * 64 + lane * 2 + 1];

    int base = 0;                                 // (16*bt) % RING
    #pragma unroll 1
    for (int bt = 0; bt < 16; ++bt) {
        const int r = bt * 16 + wid;              // this warp's input row

        // local inclusive prefix over this lane's 8 values
        float p0 = a.x;
        float p1 = p0 + a.y;
        float p2 = p1 + a.z;
        float p3 = p2 + a.w;
        float p4 = p3 + b.x;
        float p5 = p4 + b.y;
        float p6 = p5 + b.z;
        float p7 = p6 + b.w;

        // prefetch next batch's row ASAP (a,b dead) -> DRAM reads in flight
        // through scan + shuffles + stores + vertical
        if (bt < 15) {
            a = rp[(r + 16) * 64 + lane * 2];
            b = rp[(r + 16) * 64 + lane * 2 + 1];
        }

        // warp inclusive scan of lane totals
        float t = p7;
        #pragma unroll
        for (int o = 1; o < 32; o <<= 1) {
            float u = __shfl_up_sync(0xffffffffu, t, o);
            if (lane >= o) t += u;
        }
        const float e = t - p7;                   // global prefix at 8*lane-1

        // global inclusive prefixes q_k = P[8*lane+k]
        float q0 = e + p0, q1 = e + p1, q2 = e + p2, q3 = e + p3;
        float q4 = e + p4, q5 = e + p5, q6 = e + p6, q7 = e + p7;

        // H[j] = P[j+63] - P[j-1] via cross-lane differences:
        //   H[8l]   = q7(lane l+7) - e
        //   H[8l+k] = q_{k-1}(lane l+8) - q_{k-1},  k=1..7
        // lane 24's h0 = t31 - t23 = H[192].
        float s7 = __shfl_down_sync(0xffffffffu, q7, 7);
        float s0 = __shfl_down_sync(0xffffffffu, q0, 8);
        float s1 = __shfl_down_sync(0xffffffffu, q1, 8);
        float s2 = __shfl_down_sync(0xffffffffu, q2, 8);
        float s3 = __shfl_down_sync(0xffffffffu, q3, 8);
        float s4 = __shfl_down_sync(0xffffffffu, q4, 8);
        float s5 = __shfl_down_sync(0xffffffffu, q5, 8);
        float s6 = __shfl_down_sync(0xffffffffu, q6, 8);

        float h0 = s7 - e;
        float h1 = s0 - q0;
        float h2 = s1 - q1;
        float h3 = s2 - q2;
        float h4 = s3 - q3;
        float h5 = s4 - q4;
        float h6 = s5 - q5;
        float h7 = s6 - q6;

        float* Hrow = Hs + (base + wid) * HSTR;
        if (lane < 24) {
            float4 v0 = make_float4(h0, h1, h2, h3);
            float4 v1 = make_float4(h4, h5, h6, h7);
            float4* hp = (float4*)(Hrow + 8 * lane);
            hp[0] = v0;
            hp[1] = v1;
        } else if (lane == 24) {
            Hrow[192] = h0;
        }

        __syncthreads();   // H rows of batch bt visible; fences vertical(bt-1)

        // ------- vertical sliding window: 16 steps, threads 0..255 -------
        if (tid < 256) {
            const float* Hn = Hs + base * HSTR + cj;        // new rows
            if (bt < 4) {
                #pragma unroll
                for (int k = 0; k < 16; ++k)
                    vs += Hn[k * HSTR];
                if (bt == 3) {                    // vs = box[0]; y = 0..31
                    float v = vs * inv;
                    #pragma unroll
                    for (int y = 0; y < 32; ++y)
                        outImg[y * 256 + tid] = v;
                }
            } else {
                int sob = base + 32;                         // row r-64 slots
                if (sob >= RING) sob -= RING;                // never splits batch
                const float* Ho = Hs + sob * HSTR + cj;
                float* op = outImg + (bt * 16 - 32) * 256 + tid;
                #pragma unroll
                for (int k = 0; k < 16; ++k) {
                    vs += Hn[k * HSTR] - Ho[k * HSTR];
                    op[k * 256] = vs * inv;
                }
                if (bt == 15) {                   // vs = box[192]; y = 224..255
                    float v = vs * inv;
                    #pragma unroll
                    for (int y = 224; y < 256; ++y)
                        outImg[y * 256 + tid] = v;
                }
            }
        }

        base += 16;
        if (base >= RING) base -= RING;
    }
}

extern "C" void kernel_launch(void* const* d_in, const int* in_sizes, int n_in,
                              void* d_out, int out_size) {
    const float* x = (const float*)d_in[0];
    float* out = (float*)d_out;
    const int n_images = in_sizes[0] / IMG_ELEMS;   // 16*64 = 1024

    cudaFuncSetAttribute(avgpool64_v3,
                         cudaFuncAttributeMaxDynamicSharedMemorySize, SMEM_BYTES);
    avgpool64_v3<<<n_images, 512, SMEM_BYTES>>>(x, out);
}